// round 15
// baseline (speedup 1.0000x reference)
#include <cuda_runtime.h>

// Problem constants (from reference_code)
#define Hn    50000
#define INn   50000
#define NNZn  800000
#define Bn    8
#define Tn    32

#define NB    ((Hn + 255) / 256)   // 196 scan blocks per matrix
#define SP    768                  // smem hh-pair staging capacity per block
#define NCH   6                    // ih timestep chunks

// ---------------- device scratch (static globals; no runtime allocation) ----
__device__ float g_xT[(size_t)Tn * INn * Bn];      // x transposed -> (T, IN, B)
__device__ float g_ihpre[(size_t)Tn * Hn * Bn];    // ih spmm + bias, (T, H, B)
__device__ float g_h[2][Hn * Bn];                  // ping-pong hidden state (H, B)
__device__ int   g_rowptr[2][Hn + 1];              // [0]=hh, [1]=ih
__device__ int   g_cnt[2][Hn];
__device__ int   g_cur[2][Hn];
__device__ int   g_bsum[2][256];
__device__ int2  g_pairs[2][NNZn];                 // {col, float_as_int(val)}

// ---------------- preprocessing --------------------------------------------

// zero histogram counters only (h0 is never read: step 0 skips the hh gather)
__global__ void init_kernel() {
    int i = blockIdx.x * blockDim.x + threadIdx.x;
    if (i < Hn) { g_cnt[0][i] = 0; g_cnt[1][i] = 0; }
}

// fused histogram over both matrices (gridDim.y selects matrix)
__global__ void hist_kernel(const int* __restrict__ hh_idx,
                            const int* __restrict__ ih_idx) {
    int j = blockIdx.x * blockDim.x + threadIdx.x;
    int m = blockIdx.y;
    if (j >= NNZn) return;
    const int* rows = m ? ih_idx : hh_idx;
    atomicAdd(&g_cnt[m][rows[j]], 1);
}

// phase 1: per-block inclusive scan of 256 counts
__global__ void scan1_kernel() {
    int m = blockIdx.y;
    int i = blockIdx.x * 256 + threadIdx.x;
    int v = (i < Hn) ? g_cnt[m][i] : 0;
    int lane = threadIdx.x & 31, w = threadIdx.x >> 5;
    int x = v;
#pragma unroll
    for (int o = 1; o < 32; o <<= 1) {
        int y = __shfl_up_sync(~0u, x, o);
        if (lane >= o) x += y;
    }
    __shared__ int wsum[8];
    if (lane == 31) wsum[w] = x;
    __syncthreads();
    if (w == 0 && lane < 8) {
        int y = wsum[lane];
#pragma unroll
        for (int o = 1; o < 8; o <<= 1) {
            int z = __shfl_up_sync(0xffu, y, o);
            if (lane >= o) y += z;
        }
        wsum[lane] = y;
    }
    __syncthreads();
    int incl = x + (w > 0 ? wsum[w - 1] : 0);
    if (i < Hn) g_rowptr[m][i] = incl - v;          // local exclusive
    if (threadIdx.x == 255) g_bsum[m][blockIdx.x] = incl;
}

// phase 2: scan the (<=256) block sums
__global__ void scan2_kernel() {
    int m = blockIdx.y;
    int t = threadIdx.x;
    int v = (t < NB) ? g_bsum[m][t] : 0;
    int lane = t & 31, w = t >> 5;
    int x = v;
#pragma unroll
    for (int o = 1; o < 32; o <<= 1) {
        int y = __shfl_up_sync(~0u, x, o);
        if (lane >= o) x += y;
    }
    __shared__ int wsum[8];
    if (lane == 31) wsum[w] = x;
    __syncthreads();
    if (w == 0 && lane < 8) {
        int y = wsum[lane];
#pragma unroll
        for (int o = 1; o < 8; o <<= 1) {
            int z = __shfl_up_sync(0xffu, y, o);
            if (lane >= o) y += z;
        }
        wsum[lane] = y;
    }
    __syncthreads();
    int incl = x + (w > 0 ? wsum[w - 1] : 0);
    if (t < NB) g_bsum[m][t] = incl - v;
    if (t == 255) g_rowptr[m][Hn] = incl;           // total nnz
}

// phase 3: add block offsets; materialize rowptr + scatter cursor
__global__ void scan3_kernel() {
    int m = blockIdx.y;
    int i = blockIdx.x * 256 + threadIdx.x;
    if (i >= Hn) return;
    int r = g_rowptr[m][i] + g_bsum[m][blockIdx.x];
    g_rowptr[m][i] = r;
    g_cur[m][i]    = r;
}

// fused scatter into CSR pair arrays (gridDim.y selects matrix)
__global__ void scatter_kernel(const int* __restrict__ hh_idx,
                               const float* __restrict__ hh_vals,
                               const int* __restrict__ ih_idx,
                               const float* __restrict__ ih_vals) {
    int j = blockIdx.x * blockDim.x + threadIdx.x;
    int m = blockIdx.y;
    if (j >= NNZn) return;
    const int*   idx  = m ? ih_idx  : hh_idx;
    const float* vals = m ? ih_vals : hh_vals;
    int r = idx[j];
    int c = idx[NNZn + j];
    int p = atomicAdd(&g_cur[m][r], 1);
    g_pairs[m][p] = make_int2(c, __float_as_int(vals[j]));
}

// x (B, T, IN) -> g_xT (T, IN, B). Runs on stream2 CONCURRENTLY with the
// CSR build (reads only the raw input x).
__global__ void transpose_kernel(const float* __restrict__ x) {
    int idx = blockIdx.x * blockDim.x + threadIdx.x;   // over T*IN
    if (idx >= Tn * INn) return;
    int t = idx / INn;
    int c = idx - t * INn;
    float v[Bn];
#pragma unroll
    for (int b = 0; b < Bn; ++b)
        v[b] = x[(size_t)b * Tn * INn + (size_t)t * INn + c];
    float4* dst = reinterpret_cast<float4*>(&g_xT[(size_t)idx * Bn]);
    dst[0] = make_float4(v[0], v[1], v[2], v[3]);
    dst[1] = make_float4(v[4], v[5], v[6], v[7]);
}

// ---------------- main compute ---------------------------------------------

// ih chunk: ihpre[t, r, b] = bias[r] + sum_j ih_val[j] * xT[t, col[j], b]
// for t in [t0, t1), t1 - t0 <= 8. Runs on stream2, overlapping the step
// chain; per-chunk pair re-read lives entirely in the overlapped region.
__global__ void ih_chunk_kernel(const float* __restrict__ bias, int t0, int t1) {
    int g = blockIdx.x * 32 + (threadIdx.x >> 3);      // row
    if (g >= Hn) return;
    int b = threadIdx.x & 7;
    float bv = bias[g];
    float acc[8];
#pragma unroll
    for (int k = 0; k < 8; ++k) acc[k] = bv;
    const int nt = t1 - t0;
    int jb = g_rowptr[1][g];
    int je = g_rowptr[1][g + 1];
    const float* xbase = g_xT + (size_t)t0 * INn * Bn + b;
    for (int j = jb; j < je; ++j) {
        int2 p = g_pairs[1][j];
        float v = __int_as_float(p.y);
        const float* xp = xbase + (size_t)p.x * Bn;
#pragma unroll
        for (int k = 0; k < 8; ++k)
            if (k < nt) acc[k] += v * xp[(size_t)k * INn * Bn];
    }
    for (int k = 0; k < nt; ++k)
        g_ihpre[((size_t)(t0 + k) * Hn + g) * Bn + b] = acc[k];
}

// step 0 special case: h0 == 0 so hh @ h0 == 0 -> h1 = tanh(ihpre[0]).
// No pair staging, no gather loop. Writes h[1] and out slice t=0.
__global__ void __launch_bounds__(256)
step0_kernel(float* __restrict__ hnext,
             const float* __restrict__ ihpre_t,
             float* __restrict__ out_t) {
    const int g = blockIdx.x * 32 + (threadIdx.x >> 3);
    const int b = threadIdx.x & 7;
    if (g >= Hn) return;
    float hv = tanhf(ihpre_t[g * Bn + b]);
    hnext[g * Bn + b] = hv;
    cudaTriggerProgrammaticLaunchCompletion();
    out_t[(size_t)b * Tn * Hn + g] = hv;   // out layout (B, T, H)
}

// one recurrence step — champion layout: late trigger, h-independent
// prologue (pair staging + ihpre/rowptr loads) before gridsync. Block-level
// uniform smem-vs-global branch keeps the hot loop select-free.
template <bool LAST>
__global__ void __launch_bounds__(256)
step_kernel(const float* __restrict__ hprev,
            float* __restrict__ hnext,
            const float* __restrict__ ihpre_t,
            float* __restrict__ out_t) {   // d_out + t*H
    __shared__ int2 s_pairs[SP];

    const int g = blockIdx.x * 32 + (threadIdx.x >> 3);
    const int b = threadIdx.x & 7;
    const bool valid = g < Hn;

    // ---- h-independent prologue ----
    const int row0 = blockIdx.x * 32;
    const int row1 = (row0 + 32 < Hn) ? row0 + 32 : Hn;
    const int base = g_rowptr[0][row0];
    const int nnzb = g_rowptr[0][row1] - base;
    const bool use_smem = (nnzb <= SP);          // uniform across the block
    if (use_smem) {
        for (int i = threadIdx.x; i < nnzb; i += 256)
            s_pairs[i] = g_pairs[0][base + i];
    }

    float acc = 0.0f;
    int jb = 0, je = 0;
    if (valid) {
        acc = ihpre_t[g * Bn + b];
        jb = g_rowptr[0][g];
        je = g_rowptr[0][g + 1];
    }
    __syncthreads();

    // ---- wait for upstream step's hnext writes ----
    cudaGridDependencySynchronize();

    float hv = 0.0f;
    if (valid) {
        if (use_smem) {
            const int2* sp = s_pairs + (jb - base);
            const int n = je - jb;
#pragma unroll 4
            for (int k = 0; k < n; ++k) {
                int2 p = sp[k];
                acc += __int_as_float(p.y) * hprev[p.x * Bn + b];
            }
        } else {
#pragma unroll 4
            for (int j = jb; j < je; ++j) {
                int2 p = g_pairs[0][j];
                acc += __int_as_float(p.y) * hprev[p.x * Bn + b];
            }
        }
        hv = tanhf(acc);
        if (!LAST) hnext[g * Bn + b] = hv;
    }

    // allow the next step to launch; out is never read downstream
    cudaTriggerProgrammaticLaunchCompletion();

    if (valid)
        out_t[(size_t)b * Tn * Hn + g] = hv;   // out layout (B, T, H)
}

// ---------------- launch ----------------------------------------------------

extern "C" void kernel_launch(void* const* d_in, const int* in_sizes, int n_in,
                              void* d_out, int out_size) {
    const float* x        = (const float*)d_in[0];   // (B, T, IN)
    const float* hh_vals  = (const float*)d_in[1];   // (NNZ,)
    const float* hh_bias  = (const float*)d_in[2];   // (H, 1)
    const float* ih_vals  = (const float*)d_in[3];   // (NNZ,)
    const int*   hh_idx   = (const int*)d_in[4];     // (2, NNZ): rows then cols
    const int*   ih_idx   = (const int*)d_in[5];     // (2, NNZ)
    float*       out      = (float*)d_out;           // (B, T, H)

    float *ihpre_p, *h_p;
    cudaGetSymbolAddress((void**)&ihpre_p, g_ihpre);
    cudaGetSymbolAddress((void**)&h_p,     g_h);

    const int TPB = 256;

    // side stream + events (fork-join capture; handles created per call and
    // intentionally not destroyed — no device memory is allocated by these
    // APIs and the harness calls this only a handful of times.)
    cudaStream_t s2;
    cudaStreamCreateWithFlags(&s2, cudaStreamNonBlocking);
    cudaEvent_t e_pre, e_ch[NCH];
    cudaEventCreateWithFlags(&e_pre, cudaEventDisableTiming);
    for (int c = 0; c < NCH; ++c)
        cudaEventCreateWithFlags(&e_ch[c], cudaEventDisableTiming);

    static const int chunk_beg[NCH] = {0, 2, 6, 14, 22, 28};
    static const int chunk_end[NCH] = {2, 6, 14, 22, 28, 32};

    // 0) transpose on stream2, CONCURRENT with the whole CSR build
    transpose_kernel<<<(Tn * INn + TPB - 1) / TPB, TPB, 0, s2>>>(x);

    // 1) init histogram counters
    init_kernel<<<(Hn + TPB - 1) / TPB, TPB>>>();

    // 2) fused histograms
    dim3 hg((NNZn + TPB - 1) / TPB, 2);
    hist_kernel<<<hg, TPB>>>(hh_idx, ih_idx);

    // 3) hierarchical scans -> rowptr + cursor (both matrices at once)
    dim3 sg(NB, 2);
    scan1_kernel<<<sg, 256>>>();
    scan2_kernel<<<dim3(1, 2), 256>>>();
    scan3_kernel<<<sg, 256>>>();

    // 4) fused scatter into CSR pair arrays
    scatter_kernel<<<hg, TPB>>>(hh_idx, hh_vals, ih_idx, ih_vals);

    // fork: s2 (already holding transpose) waits for the CSR build, then
    // runs the ih chunks concurrently with the step chain
    cudaEventRecord(e_pre, 0);
    cudaStreamWaitEvent(s2, e_pre, 0);
    const int ih_grid = (Hn + 31) / 32;
    for (int c = 0; c < NCH; ++c) {
        ih_chunk_kernel<<<ih_grid, TPB, 0, s2>>>(hh_bias,
                                                 chunk_beg[c], chunk_end[c]);
        cudaEventRecord(e_ch[c], s2);
    }

    // 5) sequential recurrence: 32 steps, PDL-chained; step chunk_beg[c]
    //    additionally waits for ih chunk c (joins stream2 into the graph)
    const int step_grid = (Hn + 31) / 32;        // 1563 blocks

    cudaLaunchAttribute attrs[1];
    attrs[0].id = cudaLaunchAttributeProgrammaticStreamSerialization;
    attrs[0].val.programmaticStreamSerializationAllowed = 1;

    cudaLaunchConfig_t cfg = {};
    cfg.gridDim  = dim3(step_grid, 1, 1);
    cfg.blockDim = dim3(256, 1, 1);
    cfg.dynamicSmemBytes = 0;
    cfg.stream = 0;                              // legacy default stream
    cfg.attrs = attrs;
    cfg.numAttrs = 1;

    int c = 0;
    for (int t = 0; t < Tn; ++t) {
        if (c < NCH && t == chunk_beg[c]) {
            cudaStreamWaitEvent(0, e_ch[c], 0);
            ++c;
        }
        const float* hprev = h_p + (size_t)(t & 1) * Hn * Bn;
        float*       hnext = h_p + (size_t)((t + 1) & 1) * Hn * Bn;
        const float* ihp   = ihpre_p + (size_t)t * Hn * Bn;
        float*       outt  = out + (size_t)t * Hn;
        if (t == 0)
            cudaLaunchKernelEx(&cfg, step0_kernel, hnext, ihp, outt);
        else if (t + 1 < Tn)
            cudaLaunchKernelEx(&cfg, step_kernel<false>, hprev, hnext, ihp, outt);
        else
            cudaLaunchKernelEx(&cfg, step_kernel<true>,  hprev, hnext, ihp, outt);
    }
}

// round 16
// speedup vs baseline: 1.1171x; 1.1171x over previous
#include <cuda_runtime.h>

// Problem constants (from reference_code)
#define Hn    50000
#define INn   50000
#define NNZn  800000
#define Bn    8
#define Tn    32

#define NB    ((Hn + 255) / 256)   // 196 scan blocks per matrix
#define SP    1280                 // smem hh-pair staging capacity (64 rows/blk)
#define NCH   9                    // ih timestep chunks

// ---------------- device scratch (static globals; no runtime allocation) ----
__device__ float g_xT[(size_t)Tn * INn * Bn];      // x transposed -> (T, IN, B)
__device__ float g_ihpre[(size_t)Tn * Hn * Bn];    // ih spmm + bias, (T, H, B)
__device__ float g_h[2][Hn * Bn];                  // ping-pong hidden state (H, B)
__device__ int   g_rowptr[2][Hn + 1];              // [0]=hh, [1]=ih
__device__ int   g_cnt[2][Hn];
__device__ int   g_cur[2][Hn];
__device__ int   g_bsum[2][256];
__device__ int2  g_pairs[2][NNZn];                 // {col, float_as_int(val)}

// ---------------- preprocessing --------------------------------------------

// zero histogram counters only (h0 is never read: step 0 skips the hh gather)
__global__ void init_kernel() {
    int i = blockIdx.x * blockDim.x + threadIdx.x;
    if (i < Hn) { g_cnt[0][i] = 0; g_cnt[1][i] = 0; }
}

// fused histogram over both matrices (gridDim.y selects matrix)
__global__ void hist_kernel(const int* __restrict__ hh_idx,
                            const int* __restrict__ ih_idx) {
    int j = blockIdx.x * blockDim.x + threadIdx.x;
    int m = blockIdx.y;
    if (j >= NNZn) return;
    const int* rows = m ? ih_idx : hh_idx;
    atomicAdd(&g_cnt[m][rows[j]], 1);
}

// phase 1: per-block inclusive scan of 256 counts
__global__ void scan1_kernel() {
    int m = blockIdx.y;
    int i = blockIdx.x * 256 + threadIdx.x;
    int v = (i < Hn) ? g_cnt[m][i] : 0;
    int lane = threadIdx.x & 31, w = threadIdx.x >> 5;
    int x = v;
#pragma unroll
    for (int o = 1; o < 32; o <<= 1) {
        int y = __shfl_up_sync(~0u, x, o);
        if (lane >= o) x += y;
    }
    __shared__ int wsum[8];
    if (lane == 31) wsum[w] = x;
    __syncthreads();
    if (w == 0 && lane < 8) {
        int y = wsum[lane];
#pragma unroll
        for (int o = 1; o < 8; o <<= 1) {
            int z = __shfl_up_sync(0xffu, y, o);
            if (lane >= o) y += z;
        }
        wsum[lane] = y;
    }
    __syncthreads();
    int incl = x + (w > 0 ? wsum[w - 1] : 0);
    if (i < Hn) g_rowptr[m][i] = incl - v;          // local exclusive
    if (threadIdx.x == 255) g_bsum[m][blockIdx.x] = incl;
}

// phase 2: scan the (<=256) block sums
__global__ void scan2_kernel() {
    int m = blockIdx.y;
    int t = threadIdx.x;
    int v = (t < NB) ? g_bsum[m][t] : 0;
    int lane = t & 31, w = t >> 5;
    int x = v;
#pragma unroll
    for (int o = 1; o < 32; o <<= 1) {
        int y = __shfl_up_sync(~0u, x, o);
        if (lane >= o) x += y;
    }
    __shared__ int wsum[8];
    if (lane == 31) wsum[w] = x;
    __syncthreads();
    if (w == 0 && lane < 8) {
        int y = wsum[lane];
#pragma unroll
        for (int o = 1; o < 8; o <<= 1) {
            int z = __shfl_up_sync(0xffu, y, o);
            if (lane >= o) y += z;
        }
        wsum[lane] = y;
    }
    __syncthreads();
    int incl = x + (w > 0 ? wsum[w - 1] : 0);
    if (t < NB) g_bsum[m][t] = incl - v;
    if (t == 255) g_rowptr[m][Hn] = incl;           // total nnz
}

// phase 3: add block offsets; materialize rowptr + scatter cursor
__global__ void scan3_kernel() {
    int m = blockIdx.y;
    int i = blockIdx.x * 256 + threadIdx.x;
    if (i >= Hn) return;
    int r = g_rowptr[m][i] + g_bsum[m][blockIdx.x];
    g_rowptr[m][i] = r;
    g_cur[m][i]    = r;
}

// fused scatter into CSR pair arrays (gridDim.y selects matrix)
__global__ void scatter_kernel(const int* __restrict__ hh_idx,
                               const float* __restrict__ hh_vals,
                               const int* __restrict__ ih_idx,
                               const float* __restrict__ ih_vals) {
    int j = blockIdx.x * blockDim.x + threadIdx.x;
    int m = blockIdx.y;
    if (j >= NNZn) return;
    const int*   idx  = m ? ih_idx  : hh_idx;
    const float* vals = m ? ih_vals : hh_vals;
    int r = idx[j];
    int c = idx[NNZn + j];
    int p = atomicAdd(&g_cur[m][r], 1);
    g_pairs[m][p] = make_int2(c, __float_as_int(vals[j]));
}

// x (B, T, IN) -> g_xT (T, IN, B)
__global__ void transpose_kernel(const float* __restrict__ x) {
    int idx = blockIdx.x * blockDim.x + threadIdx.x;   // over T*IN
    if (idx >= Tn * INn) return;
    int t = idx / INn;
    int c = idx - t * INn;
    float v[Bn];
#pragma unroll
    for (int b = 0; b < Bn; ++b)
        v[b] = x[(size_t)b * Tn * INn + (size_t)t * INn + c];
    float4* dst = reinterpret_cast<float4*>(&g_xT[(size_t)idx * Bn]);
    dst[0] = make_float4(v[0], v[1], v[2], v[3]);
    dst[1] = make_float4(v[4], v[5], v[6], v[7]);
}

// ---------------- main compute ---------------------------------------------

// ih chunk: ihpre[t, r, b] = bias[r] + sum_j ih_val[j] * xT[t, col[j], b]
// for t in [t0, t1), t1 - t0 <= 4. Runs on stream2, overlapping the step
// chain; per-chunk pair re-read lives entirely in the overlapped region.
__global__ void ih_chunk_kernel(const float* __restrict__ bias, int t0, int t1) {
    int g = blockIdx.x * 32 + (threadIdx.x >> 3);      // row
    if (g >= Hn) return;
    int b = threadIdx.x & 7;
    float bv = bias[g];
    float acc[4] = {bv, bv, bv, bv};
    const int nt = t1 - t0;
    int jb = g_rowptr[1][g];
    int je = g_rowptr[1][g + 1];
    const float* xbase = g_xT + (size_t)t0 * INn * Bn + b;
    for (int j = jb; j < je; ++j) {
        int2 p = g_pairs[1][j];
        float v = __int_as_float(p.y);
        const float* xp = xbase + (size_t)p.x * Bn;
#pragma unroll
        for (int k = 0; k < 4; ++k)
            if (k < nt) acc[k] += v * xp[(size_t)k * INn * Bn];
    }
    for (int k = 0; k < nt; ++k)
        g_ihpre[((size_t)(t0 + k) * Hn + g) * Bn + b] = acc[k];
}

// step 0 special case: h0 == 0 so hh @ h0 == 0 -> h1 = tanh(ihpre[0]).
__global__ void __launch_bounds__(256)
step0_kernel(float* __restrict__ hnext,
             const float* __restrict__ ihpre_t,
             float* __restrict__ out_t) {
    const int g = blockIdx.x * 32 + (threadIdx.x >> 3);
    const int b = threadIdx.x & 7;
    if (g >= Hn) return;
    float hv = tanhf(ihpre_t[g * Bn + b]);
    hnext[g * Bn + b] = hv;
    cudaTriggerProgrammaticLaunchCompletion();
    out_t[(size_t)b * Tn * Hn + g] = hv;   // out layout (B, T, H)
}

// one recurrence step — float2 batch lanes: each thread covers 2 adjacent
// batch elements (b=2*lane, 2*lane+1) of one row via float2 loads. Same
// per-thread latency-chain length as the champion (16 independent gathers),
// but HALF the threads: 782 blocks x 256 thr = 200K threads -> the entire
// step grid is wave-1 resident (no second wave), with slots to spare for
// the next step's PDL-prelaunched prologues.
template <bool LAST>
__global__ void __launch_bounds__(256)
step_kernel(const float2* __restrict__ hprev2,
            float2* __restrict__ hnext2,
            const float2* __restrict__ ihpre2,
            float* __restrict__ out_t) {   // d_out + t*H
    __shared__ int2 s_pairs[SP];

    const int r    = threadIdx.x >> 2;          // row-in-block 0..63
    const int lane = threadIdx.x & 3;           // float2 batch lane
    const int g    = blockIdx.x * 64 + r;
    const bool valid = g < Hn;

    // ---- h-independent prologue ----
    const int row0 = blockIdx.x * 64;
    const int row1 = (row0 + 64 < Hn) ? row0 + 64 : Hn;
    const int base = g_rowptr[0][row0];
    const int nnzb = g_rowptr[0][row1] - base;
    const bool use_smem = (nnzb <= SP);         // uniform across the block
    if (use_smem) {
        for (int i = threadIdx.x; i < nnzb; i += 256)
            s_pairs[i] = g_pairs[0][base + i];
    }

    float2 acc = make_float2(0.0f, 0.0f);
    int jb = 0, je = 0;
    if (valid) {
        acc = ihpre2[g * 4 + lane];
        jb = g_rowptr[0][g];
        je = g_rowptr[0][g + 1];
    }
    __syncthreads();

    // ---- wait for upstream step's hnext writes ----
    cudaGridDependencySynchronize();

    float2 hv = make_float2(0.0f, 0.0f);
    if (valid) {
        if (use_smem) {
            const int2* sp = s_pairs + (jb - base);
            const int n = je - jb;
#pragma unroll 4
            for (int k = 0; k < n; ++k) {
                int2 p = sp[k];
                float v = __int_as_float(p.y);
                float2 h = hprev2[p.x * 4 + lane];
                acc.x += v * h.x;
                acc.y += v * h.y;
            }
        } else {
#pragma unroll 4
            for (int j = jb; j < je; ++j) {
                int2 p = g_pairs[0][j];
                float v = __int_as_float(p.y);
                float2 h = hprev2[p.x * 4 + lane];
                acc.x += v * h.x;
                acc.y += v * h.y;
            }
        }
        hv.x = tanhf(acc.x);
        hv.y = tanhf(acc.y);
        if (!LAST) hnext2[g * 4 + lane] = hv;
    }

    // allow the next step to launch; out is never read downstream
    cudaTriggerProgrammaticLaunchCompletion();

    if (valid) {
        const int b0 = lane * 2;
        out_t[(size_t)b0 * Tn * Hn + g]       = hv.x;   // out layout (B, T, H)
        out_t[(size_t)(b0 + 1) * Tn * Hn + g] = hv.y;
    }
}

// ---------------- launch ----------------------------------------------------

extern "C" void kernel_launch(void* const* d_in, const int* in_sizes, int n_in,
                              void* d_out, int out_size) {
    const float* x        = (const float*)d_in[0];   // (B, T, IN)
    const float* hh_vals  = (const float*)d_in[1];   // (NNZ,)
    const float* hh_bias  = (const float*)d_in[2];   // (H, 1)
    const float* ih_vals  = (const float*)d_in[3];   // (NNZ,)
    const int*   hh_idx   = (const int*)d_in[4];     // (2, NNZ): rows then cols
    const int*   ih_idx   = (const int*)d_in[5];     // (2, NNZ)
    float*       out      = (float*)d_out;           // (B, T, H)

    float *ihpre_p, *h_p;
    cudaGetSymbolAddress((void**)&ihpre_p, g_ihpre);
    cudaGetSymbolAddress((void**)&h_p,     g_h);

    const int TPB = 256;

    // side stream + events (fork-join capture; handles created per call and
    // intentionally not destroyed — no device memory is allocated by these
    // APIs and the harness calls this only a handful of times.)
    cudaStream_t s2;
    cudaStreamCreateWithFlags(&s2, cudaStreamNonBlocking);
    cudaEvent_t e_pre, e_ch[NCH];
    cudaEventCreateWithFlags(&e_pre, cudaEventDisableTiming);
    for (int c = 0; c < NCH; ++c)
        cudaEventCreateWithFlags(&e_ch[c], cudaEventDisableTiming);

    static const int chunk_beg[NCH] = {0, 2, 4, 8, 12, 16, 20, 24, 28};
    static const int chunk_end[NCH] = {2, 4, 8, 12, 16, 20, 24, 28, 32};

    // 1) init histogram counters
    init_kernel<<<(Hn + TPB - 1) / TPB, TPB>>>();

    // 2) fused histograms
    dim3 hg((NNZn + TPB - 1) / TPB, 2);
    hist_kernel<<<hg, TPB>>>(hh_idx, ih_idx);

    // 3) hierarchical scans -> rowptr + cursor (both matrices at once)
    dim3 sg(NB, 2);
    scan1_kernel<<<sg, 256>>>();
    scan2_kernel<<<dim3(1, 2), 256>>>();
    scan3_kernel<<<sg, 256>>>();

    // 4) fused scatter into CSR pair arrays
    scatter_kernel<<<hg, TPB>>>(hh_idx, hh_vals, ih_idx, ih_vals);

    // 5) transpose x -> (T, IN, B)
    transpose_kernel<<<(Tn * INn + TPB - 1) / TPB, TPB>>>(x);

    // fork stream2 after preprocessing; run ih chunks concurrently with steps
    cudaEventRecord(e_pre, 0);
    cudaStreamWaitEvent(s2, e_pre, 0);
    const int ih_grid = (Hn + 31) / 32;
    for (int c = 0; c < NCH; ++c) {
        ih_chunk_kernel<<<ih_grid, TPB, 0, s2>>>(hh_bias,
                                                 chunk_beg[c], chunk_end[c]);
        cudaEventRecord(e_ch[c], s2);
    }

    // 6) sequential recurrence: 32 steps, PDL-chained; step chunk_beg[c]
    //    additionally waits for ih chunk c (joins stream2 into the graph)
    cudaLaunchAttribute attrs[1];
    attrs[0].id = cudaLaunchAttributeProgrammaticStreamSerialization;
    attrs[0].val.programmaticStreamSerializationAllowed = 1;

    cudaLaunchConfig_t cfg = {};
    cfg.blockDim = dim3(256, 1, 1);
    cfg.dynamicSmemBytes = 0;
    cfg.stream = 0;                              // legacy default stream
    cfg.attrs = attrs;
    cfg.numAttrs = 1;

    int c = 0;
    for (int t = 0; t < Tn; ++t) {
        if (c < NCH && t == chunk_beg[c]) {
            cudaStreamWaitEvent(0, e_ch[c], 0);
            ++c;
        }
        float* hprev = h_p + (size_t)(t & 1) * Hn * Bn;
        float* hnext = h_p + (size_t)((t + 1) & 1) * Hn * Bn;
        const float* ihp = ihpre_p + (size_t)t * Hn * Bn;
        float* outt = out + (size_t)t * Hn;
        if (t == 0) {
            cfg.gridDim = dim3((Hn + 31) / 32, 1, 1);       // 1563 blocks
            cudaLaunchKernelEx(&cfg, step0_kernel, hnext, ihp, outt);
        } else if (t + 1 < Tn) {
            cfg.gridDim = dim3((Hn + 63) / 64, 1, 1);       // 782 blocks
            cudaLaunchKernelEx(&cfg, step_kernel<false>,
                               (const float2*)hprev, (float2*)hnext,
                               (const float2*)ihp, outt);
        } else {
            cfg.gridDim = dim3((Hn + 63) / 64, 1, 1);
            cudaLaunchKernelEx(&cfg, step_kernel<true>,
                               (const float2*)hprev, (float2*)hnext,
                               (const float2*)ihp, outt);
        }
    }
}